// round 5
// baseline (speedup 1.0000x reference)
#include <cuda_runtime.h>
#include <math.h>

// ---------------- problem constants ----------------
#define BB    8
#define LSEQ  1024            // 2*L_IN
#define ROWS  (BB*LSEQ)       // 8192 tokens
#define CC    512
#define DI    1024
#define DS    16
#define NDEPTH 4

// ---------------- scratch (device globals; no allocs allowed) ----------------
__device__ float g_up_tmp[4096*1024];   // up GEMM raw output [b*512+l, o*2+k]
__device__ float g_up   [ROWS*CC];      // rearranged up tokens
__device__ float g_h    [ROWS*CC];      // h1 / post-rms-silu
__device__ float g_x    [ROWS*CC];      // residual stream
__device__ float g_ln   [ROWS*CC];      // per-layer layernorm out
__device__ float g_xz   [ROWS*2*DI];    // in_proj out (xc_raw | z)
__device__ float g_xc   [ROWS*DI];      // conv+silu out (u)
__device__ float g_xdbc [ROWS*64];      // x_proj out (dtp|B|C)
__device__ float g_dt   [ROWS*DI];      // softplus dt
__device__ float g_y    [ROWS*DI];      // scan out * silu(z)

// ---------------- helpers ----------------
__device__ __forceinline__ float softplusf(float x) {
    return (x > 20.f) ? x : log1pf(__expf(x));
}
__device__ __forceinline__ float siluf(float x) {
    return x / (1.f + __expf(-x));
}

// ---------------- generic tiled SGEMM ----------------
// C[M,N] = A[M,K(lda)] * op(B) (+bias[col]) (+rowvec[(row>>10)*ldc+col]) (+beta*C) (softplus)
// BKXN=false: B is [N,K] row-major (computes A @ B^T)  -- the usual weight layout
// BKXN=true : B is [K,N] row-major (computes A @ B)    -- used for w_up
template<bool BKXN>
__global__ __launch_bounds__(256)
void sgemm_k(const float* __restrict__ A, int lda,
             const float* __restrict__ B, int ldb,
             float* __restrict__ C, int ldc,
             const float* __restrict__ bias,
             const float* __restrict__ rowvec,
             int M, int N, int K,
             int beta, int do_softplus)
{
    __shared__ float As[8][128];
    __shared__ float Bs[8][128];

    const int tid = threadIdx.x;
    const int m0 = blockIdx.y * 128;
    const int n0 = blockIdx.x * 128;
    const int ty = tid >> 4;      // 0..15
    const int tx = tid & 15;      // 0..15

    float acc[8][8];
#pragma unroll
    for (int i = 0; i < 8; i++)
#pragma unroll
        for (int j = 0; j < 8; j++) acc[i][j] = 0.f;

    const int ar = tid >> 1;            // 0..127
    const int ac = (tid & 1) * 4;       // 0 or 4
    const int bk  = tid >> 5;           // 0..7   (BKXN)
    const int bn4 = (tid & 31) * 4;     // 0..124 (BKXN)
    const int bn  = tid >> 1;           // 0..127 (B^T)
    const int bc  = (tid & 1) * 4;      // 0 or 4 (B^T)

    for (int k0 = 0; k0 < K; k0 += 8) {
        // A tile (M,K multiples of 128/8 in this problem -> no guards)
        float4 av = *(const float4*)(A + (size_t)(m0 + ar) * lda + k0 + ac);
        As[ac + 0][ar] = av.x; As[ac + 1][ar] = av.y;
        As[ac + 2][ar] = av.z; As[ac + 3][ar] = av.w;

        if (BKXN) {
            float4 bv = make_float4(0.f, 0.f, 0.f, 0.f);
            if (n0 + bn4 < N)
                bv = *(const float4*)(B + (size_t)(k0 + bk) * ldb + n0 + bn4);
            *(float4*)&Bs[bk][bn4] = bv;
        } else {
            float4 bv = make_float4(0.f, 0.f, 0.f, 0.f);
            if (n0 + bn < N)
                bv = *(const float4*)(B + (size_t)(n0 + bn) * ldb + k0 + bc);
            Bs[bc + 0][bn] = bv.x; Bs[bc + 1][bn] = bv.y;
            Bs[bc + 2][bn] = bv.z; Bs[bc + 3][bn] = bv.w;
        }
        __syncthreads();

#pragma unroll
        for (int kk = 0; kk < 8; kk++) {
            float arr[8], brr[8];
            *(float4*)&arr[0] = *(const float4*)&As[kk][ty * 8];
            *(float4*)&arr[4] = *(const float4*)&As[kk][ty * 8 + 4];
            *(float4*)&brr[0] = *(const float4*)&Bs[kk][tx * 8];
            *(float4*)&brr[4] = *(const float4*)&Bs[kk][tx * 8 + 4];
#pragma unroll
            for (int i = 0; i < 8; i++)
#pragma unroll
                for (int j = 0; j < 8; j++)
                    acc[i][j] = fmaf(arr[i], brr[j], acc[i][j]);
        }
        __syncthreads();
    }

    const int col = n0 + tx * 8;
    if (col >= N) return;   // N is a multiple of 8; 8-col block fully in/out

#pragma unroll
    for (int i = 0; i < 8; i++) {
        const int row = m0 + ty * 8 + i;
        float* cp = C + (size_t)row * ldc + col;
        float v[8];
#pragma unroll
        for (int j = 0; j < 8; j++) {
            float t = acc[i][j];
            if (bias)   t += bias[col + j];
            if (rowvec) t += rowvec[(row >> 10) * ldc + col + j];
            if (beta)   t += cp[j];
            if (do_softplus) t = softplusf(t);
            v[j] = t;
        }
        *(float4*)cp       = *(float4*)&v[0];
        *(float4*)(cp + 4) = *(float4*)&v[4];
    }
}

// ---------------- layernorm (C = 512, 128 threads/row) ----------------
__global__ void layernorm_k(const float* __restrict__ x,
                            const float* __restrict__ w,
                            const float* __restrict__ b,
                            float* __restrict__ out)
{
    const int row = blockIdx.x;
    const int tid = threadIdx.x;
    float4 v = ((const float4*)(x + (size_t)row * 512))[tid];
    float s  = v.x + v.y + v.z + v.w;
    float sq = v.x * v.x + v.y * v.y + v.z * v.z + v.w * v.w;
#pragma unroll
    for (int o = 16; o > 0; o >>= 1) {
        s  += __shfl_xor_sync(0xffffffffu, s,  o);
        sq += __shfl_xor_sync(0xffffffffu, sq, o);
    }
    __shared__ float ss[4], ssq[4];
    const int wid = tid >> 5;
    if ((tid & 31) == 0) { ss[wid] = s; ssq[wid] = sq; }
    __syncthreads();
    s  = ss[0]  + ss[1]  + ss[2]  + ss[3];
    sq = ssq[0] + ssq[1] + ssq[2] + ssq[3];
    const float m   = s  * (1.f / 512.f);
    const float var = sq * (1.f / 512.f) - m * m;
    const float inv = rsqrtf(var + 1e-5f);
    float4 wv = ((const float4*)w)[tid];
    float4 bv = ((const float4*)b)[tid];
    float4 o4;
    o4.x = (v.x - m) * inv * wv.x + bv.x;
    o4.y = (v.y - m) * inv * wv.y + bv.y;
    o4.z = (v.z - m) * inv * wv.z + bv.z;
    o4.w = (v.w - m) * inv * wv.w + bv.w;
    ((float4*)(out + (size_t)row * 512))[tid] = o4;
}

// ---------------- rmsnorm + silu, in place (C = 512) ----------------
__global__ void rmsnorm_silu_k(float* __restrict__ x, const float* __restrict__ w)
{
    const int row = blockIdx.x;
    const int tid = threadIdx.x;
    float4 v = ((const float4*)(x + (size_t)row * 512))[tid];
    float sq = v.x * v.x + v.y * v.y + v.z * v.z + v.w * v.w;
#pragma unroll
    for (int o = 16; o > 0; o >>= 1) sq += __shfl_xor_sync(0xffffffffu, sq, o);
    __shared__ float ssq[4];
    const int wid = tid >> 5;
    if ((tid & 31) == 0) ssq[wid] = sq;
    __syncthreads();
    sq = ssq[0] + ssq[1] + ssq[2] + ssq[3];
    const float inv = rsqrtf(sq * (1.f / 512.f) + 1e-5f);
    float4 wv = ((const float4*)w)[tid];
    float4 o4;
    float a;
    a = v.x * inv * wv.x; o4.x = siluf(a);
    a = v.y * inv * wv.y; o4.y = siluf(a);
    a = v.z * inv * wv.z; o4.z = siluf(a);
    a = v.w * inv * wv.w; o4.w = siluf(a);
    ((float4*)(x + (size_t)row * 512))[tid] = o4;
}

// ---------------- up rearrange: [b,l, o*2+k] -> [b, 2l+k, o] (+b_up) ----------------
__global__ void up_rearrange_k(const float* __restrict__ up_tmp,
                               const float* __restrict__ b_up,
                               float* __restrict__ up)
{
    const int idx  = blockIdx.x * blockDim.x + threadIdx.x;  // ROWS*512
    const int o    = idx & 511;
    const int orow = idx >> 9;
    const int b    = orow >> 10;
    const int t    = orow & 1023;
    const int l    = t >> 1;
    const int k    = t & 1;
    up[idx] = up_tmp[(size_t)(b * 512 + l) * 1024 + o * 2 + k] + b_up[o];
}

// ---------------- causal depthwise conv(4) + bias + silu ----------------
__global__ void conv_silu_k(const float* __restrict__ xz,   // [ROWS, 2048], cols 0..1023 = xc_raw
                            const float* __restrict__ cw,   // [1024,4]
                            const float* __restrict__ cb,   // [1024]
                            float* __restrict__ xc)         // [ROWS, 1024]
{
    const int idx = blockIdx.x * blockDim.x + threadIdx.x;   // ROWS*1024
    const int d   = idx & 1023;
    const int row = idx >> 10;
    const int t   = row & 1023;
    float acc = cb[d];
#pragma unroll
    for (int j = 0; j < 4; j++) {
        const int tt = t - 3 + j;
        if (tt >= 0)
            acc = fmaf(cw[d * 4 + j], xz[(size_t)(row - 3 + j) * 2048 + d], acc);
    }
    xc[idx] = siluf(acc);
}

// ---------------- selective scan ----------------
// 2 threads per (b,d): lanes (2k, 2k+1) split the 16 states (8 each).
// y_out = (sum_n h_n*C_n + u*D) * silu(z)
__global__ void scan_k(const float* __restrict__ dt,     // [ROWS,1024]
                       const float* __restrict__ xc,     // u [ROWS,1024]
                       const float* __restrict__ xz,     // z at col 1024+d, ld 2048
                       const float* __restrict__ xdbc,   // [ROWS,64]
                       const float* __restrict__ A_log,  // [1024,16] this layer
                       const float* __restrict__ Dp,     // [1024]
                       float* __restrict__ y)            // [ROWS,1024]
{
    const int tid    = threadIdx.x;       // 128
    const int half   = tid & 1;
    const int dloc   = tid >> 1;          // 0..63
    const int b      = blockIdx.x >> 4;
    const int dchunk = blockIdx.x & 15;
    const int d      = dchunk * 64 + dloc;
    const int n0     = half * 8;

    float A2[8], h[8];
#pragma unroll
    for (int j = 0; j < 8; j++) {
        A2[j] = -__expf(A_log[d * 16 + n0 + j]) * 1.44269504f;  // A * log2(e)
        h[j]  = 0.f;
    }
    const float Dd = Dp[d];

    const float* dtp = dt   + (size_t)b * 1024 * 1024 + d;
    const float* up  = xc   + (size_t)b * 1024 * 1024 + d;
    const float* zp  = xz   + (size_t)b * 1024 * 2048 + 1024 + d;
    const float* bcp = xdbc + (size_t)b * 1024 * 64   + 32 + n0;
    float*       yp  = y    + (size_t)b * 1024 * 1024 + d;

    for (int t = 0; t < 1024; t++) {
        const float dtv = dtp[(size_t)t * 1024];
        const float u   = up [(size_t)t * 1024];
        const float zv  = zp [(size_t)t * 2048];
        const float4 B0 = *(const float4*)(bcp + (size_t)t * 64);
        const float4 B1 = *(const float4*)(bcp + (size_t)t * 64 + 4);
        const float4 C0 = *(const float4*)(bcp + (size_t)t * 64 + 16);
        const float4 C1 = *(const float4*)(bcp + (size_t)t * 64 + 20);
        const float Bv[8] = {B0.x, B0.y, B0.z, B0.w, B1.x, B1.y, B1.z, B1.w};
        const float Cv[8] = {C0.x, C0.y, C0.z, C0.w, C1.x, C1.y, C1.z, C1.w};
        const float du = dtv * u;
        float ya = 0.f, yb2 = 0.f;
#pragma unroll
        for (int j = 0; j < 8; j++) {
            const float dA = exp2f(dtv * A2[j]);        // exp(dt*A)
            h[j] = fmaf(dA, h[j], du * Bv[j]);
            if (j & 1) yb2 = fmaf(h[j], Cv[j], yb2);
            else       ya  = fmaf(h[j], Cv[j], ya);
        }
        float ysum = ya + yb2;
        ysum += __shfl_xor_sync(0xffffffffu, ysum, 1);  // combine the two state halves
        if (half == 0)
            yp[(size_t)t * 1024] = (ysum + u * Dd) * siluf(zv);
    }
}

// ---------------- launcher ----------------
extern "C" void kernel_launch(void* const* d_in, const int* in_sizes, int n_in,
                              void* d_out, int out_size)
{
    (void)in_sizes; (void)n_in; (void)out_size;

    const float* motion     = (const float*)d_in[0];
    const float* skip       = (const float*)d_in[1];
    const float* embed      = (const float*)d_in[2];
    const float* w_up       = (const float*)d_in[3];
    const float* b_up       = (const float*)d_in[4];
    const float* w1         = (const float*)d_in[5];
    const float* b1         = (const float*)d_in[6];
    const float* rms_w      = (const float*)d_in[7];
    const float* w2         = (const float*)d_in[8];
    const float* b2         = (const float*)d_in[9];
    const float* ln_w       = (const float*)d_in[10];
    const float* ln_b       = (const float*)d_in[11];
    const float* in_proj_w  = (const float*)d_in[12];
    const float* conv_w     = (const float*)d_in[13];
    const float* conv_b     = (const float*)d_in[14];
    const float* x_proj_w   = (const float*)d_in[15];
    const float* dt_proj_w  = (const float*)d_in[16];
    const float* dt_proj_b  = (const float*)d_in[17];
    const float* A_log      = (const float*)d_in[18];
    const float* D_param    = (const float*)d_in[19];
    const float* out_proj_w = (const float*)d_in[20];
    const float* out_proj_b = (const float*)d_in[21];
    const float* norm_f_w   = (const float*)d_in[22];
    const float* norm_f_b   = (const float*)d_in[23];
    float* out = (float*)d_out;

    float *up_tmp, *up, *h, *x, *ln, *xz, *xc, *xdbc, *dtb, *yb;
    cudaGetSymbolAddress((void**)&up_tmp, g_up_tmp);
    cudaGetSymbolAddress((void**)&up,     g_up);
    cudaGetSymbolAddress((void**)&h,      g_h);
    cudaGetSymbolAddress((void**)&x,      g_x);
    cudaGetSymbolAddress((void**)&ln,     g_ln);
    cudaGetSymbolAddress((void**)&xz,     g_xz);
    cudaGetSymbolAddress((void**)&xc,     g_xc);
    cudaGetSymbolAddress((void**)&xdbc,   g_xdbc);
    cudaGetSymbolAddress((void**)&dtb,    g_dt);
    cudaGetSymbolAddress((void**)&yb,     g_y);

    // 1) up = motion @ w_up   (A[4096,512] @ B[512,1024] K-major)
    sgemm_k<true><<<dim3(1024/128, 4096/128), 256>>>(
        motion, 512, w_up, 1024, up_tmp, 1024,
        nullptr, nullptr, 4096, 1024, 512, 0, 0);

    // 2) rearrange [b,l,(o,k)] -> tokens, add b_up
    up_rearrange_k<<<(ROWS * 512) / 256, 256>>>(up_tmp, b_up, up);

    // 3) h = up @ w1[:, :512]^T + b1 ; h += skip @ w1[:, 512:]^T
    sgemm_k<false><<<dim3(4, 64), 256>>>(
        up, 512, w1, 1024, h, 512, b1, nullptr, ROWS, 512, 512, 0, 0);
    sgemm_k<false><<<dim3(4, 64), 256>>>(
        skip, 512, w1 + 512, 1024, h, 512, nullptr, nullptr, ROWS, 512, 512, 1, 0);

    // 4) h = silu(rmsnorm(h, rms_w)) in place
    rmsnorm_silu_k<<<ROWS, 128>>>(h, rms_w);

    // 5) x = h @ w2^T + b2 + embed[b]
    sgemm_k<false><<<dim3(4, 64), 256>>>(
        h, 512, w2, 512, x, 512, b2, embed, ROWS, 512, 512, 0, 0);

    // 6) mamba layers
    for (int i = 0; i < NDEPTH; i++) {
        layernorm_k<<<ROWS, 128>>>(x, ln_w + i * 512, ln_b + i * 512, ln);

        sgemm_k<false><<<dim3(16, 64), 256>>>(
            ln, 512, in_proj_w + (size_t)i * 2048 * 512, 512,
            xz, 2048, nullptr, nullptr, ROWS, 2048, 512, 0, 0);

        conv_silu_k<<<(ROWS * DI) / 256, 256>>>(
            xz, conv_w + (size_t)i * 1024 * 4, conv_b + i * 1024, xc);

        sgemm_k<false><<<dim3(1, 64), 256>>>(
            xc, 1024, x_proj_w + (size_t)i * 64 * 1024, 1024,
            xdbc, 64, nullptr, nullptr, ROWS, 64, 1024, 0, 0);

        sgemm_k<false><<<dim3(8, 64), 256>>>(
            xdbc, 64, dt_proj_w + (size_t)i * 1024 * 32, 32,
            dtb, 1024, dt_proj_b + i * 1024, nullptr, ROWS, 1024, 32, 0, 1);

        scan_k<<<128, 128>>>(
            dtb, xc, xz, xdbc,
            A_log + (size_t)i * 1024 * 16, D_param + i * 1024, yb);

        sgemm_k<false><<<dim3(4, 64), 256>>>(
            yb, 1024, out_proj_w + (size_t)i * 512 * 1024, 1024,
            x, 512, out_proj_b + i * 512, nullptr, ROWS, 512, 1024, 1, 0);
    }

    // 7) final layernorm -> output
    layernorm_k<<<ROWS, 128>>>(x, norm_f_w, norm_f_b, out);
}

// round 6
// speedup vs baseline: 1.8459x; 1.8459x over previous
#include <cuda_runtime.h>
#include <math.h>

// ---------------- problem constants ----------------
#define BB    8
#define LSEQ  1024            // 2*L_IN
#define ROWS  (BB*LSEQ)       // 8192 tokens
#define CC    512
#define DI    1024
#define DS    16
#define NDEPTH 4

// ---------------- scratch (device globals; no allocs allowed) ----------------
__device__ float g_up_tmp[4096*1024];   // up GEMM raw output [b*512+l, o*2+k]
__device__ float g_up   [ROWS*CC];      // rearranged up tokens
__device__ float g_h    [ROWS*CC];      // h1 / post-rms-silu
__device__ float g_x    [ROWS*CC];      // residual stream
__device__ float g_ln   [ROWS*CC];      // per-layer layernorm out
__device__ float g_xz   [ROWS*2*DI];    // in_proj out (xc_raw | z)
__device__ float g_xc   [ROWS*DI];      // conv+silu out (u)
__device__ float g_xdbc [ROWS*64];      // x_proj out (dtp|B|C)
__device__ float g_dt   [ROWS*DI];      // softplus dt
__device__ float g_y    [ROWS*DI];      // scan out * silu(z)

// ---------------- helpers ----------------
__device__ __forceinline__ float softplusf(float x) {
    return (x > 20.f) ? x : log1pf(__expf(x));
}
__device__ __forceinline__ float siluf(float x) {
    return x / (1.f + __expf(-x));
}

// ---------------- tiled SGEMM, BK=16, double-buffered smem ----------------
// C[M,N] = A[M,K(lda)] * op(B) (+bias[col]) (+rowvec[(row>>10)*ldc+col]) (+beta*C) (softplus)
// BKXN=false: B is [N,K] row-major (A @ B^T)
// BKXN=true : B is [K,N] row-major (A @ B)   -- used for w_up
template<bool BKXN>
__global__ __launch_bounds__(256, 2)
void sgemm_k(const float* __restrict__ A, int lda,
             const float* __restrict__ B, int ldb,
             float* __restrict__ C, int ldc,
             const float* __restrict__ bias,
             const float* __restrict__ rowvec,
             int M, int N, int K,
             int beta, int do_softplus)
{
    __shared__ float As[2][16][128];
    __shared__ float Bs[2][16][128];

    const int tid = threadIdx.x;
    const int m0 = blockIdx.y * 128;
    const int n0 = blockIdx.x * 128;
    const int ty = tid >> 4;      // 0..15
    const int tx = tid & 15;      // 0..15

    // A staging: each thread 2 float4 -> rows (tid>>2, tid>>2+64), cols (tid&3)*4
    const int a_r = tid >> 2;          // 0..63
    const int a_c = (tid & 3) * 4;     // 0,4,8,12
    // B NK staging: same pattern over n-rows
    const int b_r = a_r;
    const int b_c = a_c;
    // B KN staging: rows tid>>5 (+8), cols (tid&31)*4
    const int bk_r = tid >> 5;         // 0..7
    const int bk_c = (tid & 31) * 4;   // 0..124

    float acc[8][8];
#pragma unroll
    for (int i = 0; i < 8; i++)
#pragma unroll
        for (int j = 0; j < 8; j++) acc[i][j] = 0.f;

    const float* Ab = A + (size_t)m0 * lda;

    float4 a0, a1, b0, b1;

    // ---- prologue: stage k0 = 0 ----
    a0 = *(const float4*)(Ab + (size_t)a_r * lda + a_c);
    a1 = *(const float4*)(Ab + (size_t)(a_r + 64) * lda + a_c);
    if (BKXN) {
        b0 = make_float4(0.f, 0.f, 0.f, 0.f); b1 = b0;
        if (n0 + bk_c < N) {
            b0 = *(const float4*)(B + (size_t)bk_r * ldb + n0 + bk_c);
            b1 = *(const float4*)(B + (size_t)(bk_r + 8) * ldb + n0 + bk_c);
        }
    } else {
        b0 = make_float4(0.f, 0.f, 0.f, 0.f); b1 = b0;
        if (n0 + b_r < N)
            b0 = *(const float4*)(B + (size_t)(n0 + b_r) * ldb + b_c);
        if (n0 + b_r + 64 < N)
            b1 = *(const float4*)(B + (size_t)(n0 + b_r + 64) * ldb + b_c);
    }
    {
        As[0][a_c + 0][a_r] = a0.x; As[0][a_c + 1][a_r] = a0.y;
        As[0][a_c + 2][a_r] = a0.z; As[0][a_c + 3][a_r] = a0.w;
        As[0][a_c + 0][a_r + 64] = a1.x; As[0][a_c + 1][a_r + 64] = a1.y;
        As[0][a_c + 2][a_r + 64] = a1.z; As[0][a_c + 3][a_r + 64] = a1.w;
        if (BKXN) {
            *(float4*)&Bs[0][bk_r][bk_c]     = b0;
            *(float4*)&Bs[0][bk_r + 8][bk_c] = b1;
        } else {
            Bs[0][b_c + 0][b_r] = b0.x; Bs[0][b_c + 1][b_r] = b0.y;
            Bs[0][b_c + 2][b_r] = b0.z; Bs[0][b_c + 3][b_r] = b0.w;
            Bs[0][b_c + 0][b_r + 64] = b1.x; Bs[0][b_c + 1][b_r + 64] = b1.y;
            Bs[0][b_c + 2][b_r + 64] = b1.z; Bs[0][b_c + 3][b_r + 64] = b1.w;
        }
    }
    __syncthreads();

    int buf = 0;
    for (int k0 = 0; k0 < K; k0 += 16) {
        const bool nxt = (k0 + 16 < K);
        // prefetch next tile into registers (overlaps with FFMA below)
        if (nxt) {
            const int kn = k0 + 16;
            a0 = *(const float4*)(Ab + (size_t)a_r * lda + kn + a_c);
            a1 = *(const float4*)(Ab + (size_t)(a_r + 64) * lda + kn + a_c);
            if (BKXN) {
                b0 = make_float4(0.f, 0.f, 0.f, 0.f); b1 = b0;
                if (n0 + bk_c < N) {
                    b0 = *(const float4*)(B + (size_t)(kn + bk_r) * ldb + n0 + bk_c);
                    b1 = *(const float4*)(B + (size_t)(kn + bk_r + 8) * ldb + n0 + bk_c);
                }
            } else {
                b0 = make_float4(0.f, 0.f, 0.f, 0.f); b1 = b0;
                if (n0 + b_r < N)
                    b0 = *(const float4*)(B + (size_t)(n0 + b_r) * ldb + kn + b_c);
                if (n0 + b_r + 64 < N)
                    b1 = *(const float4*)(B + (size_t)(n0 + b_r + 64) * ldb + kn + b_c);
            }
        }

#pragma unroll
        for (int kk = 0; kk < 16; kk++) {
            float arr[8], brr[8];
            *(float4*)&arr[0] = *(const float4*)&As[buf][kk][ty * 8];
            *(float4*)&arr[4] = *(const float4*)&As[buf][kk][ty * 8 + 4];
            *(float4*)&brr[0] = *(const float4*)&Bs[buf][kk][tx * 8];
            *(float4*)&brr[4] = *(const float4*)&Bs[buf][kk][tx * 8 + 4];
#pragma unroll
            for (int i = 0; i < 8; i++)
#pragma unroll
                for (int j = 0; j < 8; j++)
                    acc[i][j] = fmaf(arr[i], brr[j], acc[i][j]);
        }

        if (nxt) {
            const int nb = buf ^ 1;
            As[nb][a_c + 0][a_r] = a0.x; As[nb][a_c + 1][a_r] = a0.y;
            As[nb][a_c + 2][a_r] = a0.z; As[nb][a_c + 3][a_r] = a0.w;
            As[nb][a_c + 0][a_r + 64] = a1.x; As[nb][a_c + 1][a_r + 64] = a1.y;
            As[nb][a_c + 2][a_r + 64] = a1.z; As[nb][a_c + 3][a_r + 64] = a1.w;
            if (BKXN) {
                *(float4*)&Bs[nb][bk_r][bk_c]     = b0;
                *(float4*)&Bs[nb][bk_r + 8][bk_c] = b1;
            } else {
                Bs[nb][b_c + 0][b_r] = b0.x; Bs[nb][b_c + 1][b_r] = b0.y;
                Bs[nb][b_c + 2][b_r] = b0.z; Bs[nb][b_c + 3][b_r] = b0.w;
                Bs[nb][b_c + 0][b_r + 64] = b1.x; Bs[nb][b_c + 1][b_r + 64] = b1.y;
                Bs[nb][b_c + 2][b_r + 64] = b1.z; Bs[nb][b_c + 3][b_r + 64] = b1.w;
            }
            __syncthreads();
            buf = nb;
        }
    }

    const int col = n0 + tx * 8;
    if (col >= N) return;   // N multiple of 8; 8-col block fully in/out

#pragma unroll
    for (int i = 0; i < 8; i++) {
        const int row = m0 + ty * 8 + i;
        float* cp = C + (size_t)row * ldc + col;
        float v[8];
#pragma unroll
        for (int j = 0; j < 8; j++) {
            float t = acc[i][j];
            if (bias)   t += bias[col + j];
            if (rowvec) t += rowvec[(row >> 10) * ldc + col + j];
            if (beta)   t += cp[j];
            if (do_softplus) t = softplusf(t);
            v[j] = t;
        }
        *(float4*)cp       = *(float4*)&v[0];
        *(float4*)(cp + 4) = *(float4*)&v[4];
    }
}

// ---------------- layernorm (C = 512, 128 threads/row) ----------------
__global__ void layernorm_k(const float* __restrict__ x,
                            const float* __restrict__ w,
                            const float* __restrict__ b,
                            float* __restrict__ out)
{
    const int row = blockIdx.x;
    const int tid = threadIdx.x;
    float4 v = ((const float4*)(x + (size_t)row * 512))[tid];
    float s  = v.x + v.y + v.z + v.w;
    float sq = v.x * v.x + v.y * v.y + v.z * v.z + v.w * v.w;
#pragma unroll
    for (int o = 16; o > 0; o >>= 1) {
        s  += __shfl_xor_sync(0xffffffffu, s,  o);
        sq += __shfl_xor_sync(0xffffffffu, sq, o);
    }
    __shared__ float ss[4], ssq[4];
    const int wid = tid >> 5;
    if ((tid & 31) == 0) { ss[wid] = s; ssq[wid] = sq; }
    __syncthreads();
    s  = ss[0]  + ss[1]  + ss[2]  + ss[3];
    sq = ssq[0] + ssq[1] + ssq[2] + ssq[3];
    const float m   = s  * (1.f / 512.f);
    const float var = sq * (1.f / 512.f) - m * m;
    const float inv = rsqrtf(var + 1e-5f);
    float4 wv = ((const float4*)w)[tid];
    float4 bv = ((const float4*)b)[tid];
    float4 o4;
    o4.x = (v.x - m) * inv * wv.x + bv.x;
    o4.y = (v.y - m) * inv * wv.y + bv.y;
    o4.z = (v.z - m) * inv * wv.z + bv.z;
    o4.w = (v.w - m) * inv * wv.w + bv.w;
    ((float4*)(out + (size_t)row * 512))[tid] = o4;
}

// ---------------- rmsnorm + silu, in place (C = 512) ----------------
__global__ void rmsnorm_silu_k(float* __restrict__ x, const float* __restrict__ w)
{
    const int row = blockIdx.x;
    const int tid = threadIdx.x;
    float4 v = ((const float4*)(x + (size_t)row * 512))[tid];
    float sq = v.x * v.x + v.y * v.y + v.z * v.z + v.w * v.w;
#pragma unroll
    for (int o = 16; o > 0; o >>= 1) sq += __shfl_xor_sync(0xffffffffu, sq, o);
    __shared__ float ssq[4];
    const int wid = tid >> 5;
    if ((tid & 31) == 0) ssq[wid] = sq;
    __syncthreads();
    sq = ssq[0] + ssq[1] + ssq[2] + ssq[3];
    const float inv = rsqrtf(sq * (1.f / 512.f) + 1e-5f);
    float4 wv = ((const float4*)w)[tid];
    float4 o4;
    float a;
    a = v.x * inv * wv.x; o4.x = siluf(a);
    a = v.y * inv * wv.y; o4.y = siluf(a);
    a = v.z * inv * wv.z; o4.z = siluf(a);
    a = v.w * inv * wv.w; o4.w = siluf(a);
    ((float4*)(x + (size_t)row * 512))[tid] = o4;
}

// ---------------- up rearrange: [b,l, o*2+k] -> [b, 2l+k, o] (+b_up) ----------------
__global__ void up_rearrange_k(const float* __restrict__ up_tmp,
                               const float* __restrict__ b_up,
                               float* __restrict__ up)
{
    const int idx  = blockIdx.x * blockDim.x + threadIdx.x;  // ROWS*512
    const int o    = idx & 511;
    const int orow = idx >> 9;
    const int b    = orow >> 10;
    const int t    = orow & 1023;
    const int l    = t >> 1;
    const int k    = t & 1;
    up[idx] = up_tmp[(size_t)(b * 512 + l) * 1024 + o * 2 + k] + b_up[o];
}

// ---------------- causal depthwise conv(4) + bias + silu ----------------
__global__ void conv_silu_k(const float* __restrict__ xz,   // [ROWS, 2048], cols 0..1023 = xc_raw
                            const float* __restrict__ cw,   // [1024,4]
                            const float* __restrict__ cb,   // [1024]
                            float* __restrict__ xc)         // [ROWS, 1024]
{
    const int idx = blockIdx.x * blockDim.x + threadIdx.x;   // ROWS*1024
    const int d   = idx & 1023;
    const int row = idx >> 10;
    const int t   = row & 1023;
    float acc = cb[d];
#pragma unroll
    for (int j = 0; j < 4; j++) {
        const int tt = t - 3 + j;
        if (tt >= 0)
            acc = fmaf(cw[d * 4 + j], xz[(size_t)(row - 3 + j) * 2048 + d], acc);
    }
    xc[idx] = siluf(acc);
}

// ---------------- selective scan (v2: smem B/C staging + batched prefetch) ----
// 2 threads per (b,d): lanes (2k, 2k+1) split the 16 states (8 each).
// y_out = (sum_n h_n*C_n + u*D) * silu(z)
__global__ __launch_bounds__(128)
void scan_k(const float* __restrict__ dt,     // [ROWS,1024]
            const float* __restrict__ xc,     // u [ROWS,1024]
            const float* __restrict__ xz,     // z at col 1024+d, ld 2048
            const float* __restrict__ xdbc,   // [ROWS,64]
            const float* __restrict__ A_log,  // [1024,16] this layer
            const float* __restrict__ Dp,     // [1024]
            float* __restrict__ y)            // [ROWS,1024]
{
    __shared__ float bc_s[32][32];            // [t_in_chunk][B(16)|C(16)]

    const int tid    = threadIdx.x;           // 128
    const int half   = tid & 1;
    const int dloc   = tid >> 1;               // 0..63
    const int b      = blockIdx.x >> 4;
    const int d      = (blockIdx.x & 15) * 64 + dloc;
    const int n0     = half * 8;

    float A2[8], h[8];
#pragma unroll
    for (int j = 0; j < 8; j++) {
        A2[j] = -__expf(A_log[d * 16 + n0 + j]) * 1.44269504f;  // A * log2(e)
        h[j]  = 0.f;
    }
    const float Dd = Dp[d];

    const float* dtp = dt   + (size_t)b * 1024 * 1024 + d;
    const float* up  = xc   + (size_t)b * 1024 * 1024 + d;
    const float* zp  = xz   + (size_t)b * 1024 * 2048 + 1024 + d;
    const float* bcb = xdbc + (size_t)b * 1024 * 64 + 32;
    float*       yp  = y    + (size_t)b * 1024 * 1024 + d;

    const int st_t = tid >> 2;        // 0..31 (t within chunk)
    const int st_c = (tid & 3) * 8;   // 0,8,16,24

    for (int c = 0; c < 32; c++) {
        __syncthreads();
        {
            const float* src = bcb + (size_t)(c * 32 + st_t) * 64 + st_c;
            *(float4*)&bc_s[st_t][st_c]     = *(const float4*)src;
            *(float4*)&bc_s[st_t][st_c + 4] = *(const float4*)(src + 4);
        }
        __syncthreads();

#pragma unroll
        for (int s = 0; s < 4; s++) {
            const int tbase = c * 32 + s * 8;
            float dt8[8], u8[8], z8[8];
#pragma unroll
            for (int j = 0; j < 8; j++) {          // 24 independent loads in flight
                dt8[j] = dtp[(size_t)(tbase + j) * 1024];
                u8[j]  = up [(size_t)(tbase + j) * 1024];
                z8[j]  = zp [(size_t)(tbase + j) * 2048];
            }
#pragma unroll
            for (int j = 0; j < 8; j++) {
                const int tt = s * 8 + j;
                float Bv[8], Cv[8];
                *(float4*)&Bv[0] = *(const float4*)&bc_s[tt][n0];
                *(float4*)&Bv[4] = *(const float4*)&bc_s[tt][n0 + 4];
                *(float4*)&Cv[0] = *(const float4*)&bc_s[tt][16 + n0];
                *(float4*)&Cv[4] = *(const float4*)&bc_s[tt][16 + n0 + 4];
                const float dtv = dt8[j];
                const float u   = u8[j];
                const float du  = dtv * u;
                float ya = 0.f, yb2 = 0.f;
#pragma unroll
                for (int n = 0; n < 8; n++) {
                    const float dA = exp2f(dtv * A2[n]);       // exp(dt*A)
                    h[n] = fmaf(dA, h[n], du * Bv[n]);
                    if (n & 1) yb2 = fmaf(h[n], Cv[n], yb2);
                    else       ya  = fmaf(h[n], Cv[n], ya);
                }
                float ysum = ya + yb2;
                ysum += __shfl_xor_sync(0xffffffffu, ysum, 1);
                if (half == 0)
                    yp[(size_t)(tbase + j) * 1024] = (ysum + u * Dd) * siluf(z8[j]);
            }
        }
    }
}

// ---------------- launcher ----------------
extern "C" void kernel_launch(void* const* d_in, const int* in_sizes, int n_in,
                              void* d_out, int out_size)
{
    (void)in_sizes; (void)n_in; (void)out_size;

    const float* motion     = (const float*)d_in[0];
    const float* skip       = (const float*)d_in[1];
    const float* embed      = (const float*)d_in[2];
    const float* w_up       = (const float*)d_in[3];
    const float* b_up       = (const float*)d_in[4];
    const float* w1         = (const float*)d_in[5];
    const float* b1         = (const float*)d_in[6];
    const float* rms_w      = (const float*)d_in[7];
    const float* w2         = (const float*)d_in[8];
    const float* b2         = (const float*)d_in[9];
    const float* ln_w       = (const float*)d_in[10];
    const float* ln_b       = (const float*)d_in[11];
    const float* in_proj_w  = (const float*)d_in[12];
    const float* conv_w     = (const float*)d_in[13];
    const float* conv_b     = (const float*)d_in[14];
    const float* x_proj_w   = (const float*)d_in[15];
    const float* dt_proj_w  = (const float*)d_in[16];
    const float* dt_proj_b  = (const float*)d_in[17];
    const float* A_log      = (const float*)d_in[18];
    const float* D_param    = (const float*)d_in[19];
    const float* out_proj_w = (const float*)d_in[20];
    const float* out_proj_b = (const float*)d_in[21];
    const float* norm_f_w   = (const float*)d_in[22];
    const float* norm_f_b   = (const float*)d_in[23];
    float* out = (float*)d_out;

    float *up_tmp, *up, *h, *x, *ln, *xz, *xc, *xdbc, *dtb, *yb;
    cudaGetSymbolAddress((void**)&up_tmp, g_up_tmp);
    cudaGetSymbolAddress((void**)&up,     g_up);
    cudaGetSymbolAddress((void**)&h,      g_h);
    cudaGetSymbolAddress((void**)&x,      g_x);
    cudaGetSymbolAddress((void**)&ln,     g_ln);
    cudaGetSymbolAddress((void**)&xz,     g_xz);
    cudaGetSymbolAddress((void**)&xc,     g_xc);
    cudaGetSymbolAddress((void**)&xdbc,   g_xdbc);
    cudaGetSymbolAddress((void**)&dtb,    g_dt);
    cudaGetSymbolAddress((void**)&yb,     g_y);

    // 1) up = motion @ w_up   (A[4096,512] @ B[512,1024] K-major)
    sgemm_k<true><<<dim3(1024/128, 4096/128), 256>>>(
        motion, 512, w_up, 1024, up_tmp, 1024,
        nullptr, nullptr, 4096, 1024, 512, 0, 0);

    // 2) rearrange [b,l,(o,k)] -> tokens, add b_up
    up_rearrange_k<<<(ROWS * 512) / 256, 256>>>(up_tmp, b_up, up);

    // 3) h = up @ w1[:, :512]^T + b1 ; h += skip @ w1[:, 512:]^T
    sgemm_k<false><<<dim3(4, 64), 256>>>(
        up, 512, w1, 1024, h, 512, b1, nullptr, ROWS, 512, 512, 0, 0);
    sgemm_k<false><<<dim3(4, 64), 256>>>(
        skip, 512, w1 + 512, 1024, h, 512, nullptr, nullptr, ROWS, 512, 512, 1, 0);

    // 4) h = silu(rmsnorm(h, rms_w)) in place
    rmsnorm_silu_k<<<ROWS, 128>>>(h, rms_w);

    // 5) x = h @ w2^T + b2 + embed[b]
    sgemm_k<false><<<dim3(4, 64), 256>>>(
        h, 512, w2, 512, x, 512, b2, embed, ROWS, 512, 512, 0, 0);

    // 6) mamba layers
    for (int i = 0; i < NDEPTH; i++) {
        layernorm_k<<<ROWS, 128>>>(x, ln_w + i * 512, ln_b + i * 512, ln);

        sgemm_k<false><<<dim3(16, 64), 256>>>(
            ln, 512, in_proj_w + (size_t)i * 2048 * 512, 512,
            xz, 2048, nullptr, nullptr, ROWS, 2048, 512, 0, 0);

        conv_silu_k<<<(ROWS * DI) / 256, 256>>>(
            xz, conv_w + (size_t)i * 1024 * 4, conv_b + i * 1024, xc);

        sgemm_k<false><<<dim3(1, 64), 256>>>(
            xc, 1024, x_proj_w + (size_t)i * 64 * 1024, 1024,
            xdbc, 64, nullptr, nullptr, ROWS, 64, 1024, 0, 0);

        sgemm_k<false><<<dim3(8, 64), 256>>>(
            xdbc, 64, dt_proj_w + (size_t)i * 1024 * 32, 32,
            dtb, 1024, dt_proj_b + i * 1024, nullptr, ROWS, 1024, 32, 0, 1);

        scan_k<<<128, 128>>>(
            dtb, xc, xz, xdbc,
            A_log + (size_t)i * 1024 * 16, D_param + i * 1024, yb);

        sgemm_k<false><<<dim3(4, 64), 256>>>(
            yb, 1024, out_proj_w + (size_t)i * 512 * 1024, 1024,
            x, 512, out_proj_b + i * 512, nullptr, ROWS, 512, 1024, 1, 0);
    }

    // 7) final layernorm -> output
    layernorm_k<<<ROWS, 128>>>(x, norm_f_w, norm_f_b, out);
}